// round 15
// baseline (speedup 1.0000x reference)
#include <cuda_runtime.h>
#include <cstdint>

// FlowNetC correlation via tf32 mma.sync band-GEMM with parity packing (R13 base).
// R15: k-group column interleave [k0,k4,k1,k5,k2,k6,k3,k7] -> B frag = 1 LDS.64
// (was 2 LDS.32), A frag setup halved; RSW 132->136 keeps both staging STS.64
// and frag LDS.64 bank-conflict-free; staging unrolled x4 for MLP.

#define HW_  9216
#define RSW  136             // row stride (words), ≡8 mod 32
#define BROWS 56
#define BP0  0
#define BP1  (BROWS*RSW + 16)          // 7632
#define PADOFF (BP1 + BROWS*RSW)       // 15248
#define PSTR 98
#define SMEM_WORDS (PADOFF + 21*PSTR + 8)
#define SMEM_BYTES (SMEM_WORDS*4)      // ~69.4 KB -> 3 CTAs/SM

static __device__ __forceinline__ uint32_t f2tf(float f) {
    uint32_t r;
    asm("cvt.rna.tf32.f32 %0, %1;" : "=r"(r) : "f"(f));
    return r;
}

static __device__ __forceinline__ void mma_tf32(float (&d)[4], const uint32_t (&a)[4],
                                                uint32_t b0, uint32_t b1) {
    asm volatile(
        "mma.sync.aligned.m16n8k8.row.col.f32.tf32.tf32.f32 "
        "{%0,%1,%2,%3}, {%4,%5,%6,%7}, {%8,%9}, {%0,%1,%2,%3};"
        : "+f"(d[0]), "+f"(d[1]), "+f"(d[2]), "+f"(d[3])
        : "r"(a[0]), "r"(a[1]), "r"(a[2]), "r"(a[3]), "r"(b0), "r"(b1));
}

// Stage one image row (128 ch x 96 x, fp32) into the two parity tiles as tf32.
// Element (c, x): tile p = x&1, row = rowoff + (x>>1),
// word pos within row = 8*(c>>3) + 2*(c&3) + ((c>>2)&1)  [k-group interleave].
// Unit w: q=w&3, xpl=(w>>2)&7, ks=(w>>5)&15, xph=w>>9; xp=xph*8+xpl;
// channels c_lo=8ks+q, c_hi=c_lo+4 -> adjacent dest words -> STS.64.
static __device__ __forceinline__ void stage_row(const float* __restrict__ g,
                                                 uint32_t* __restrict__ sm,
                                                 int rowoff, int tid)
{
    #pragma unroll 4
    for (int k = 0; k < 16; k++) {
        const int w   = tid + 192 * k;
        const int q   = w & 3;
        const int xpl = (w >> 2) & 7;
        const int ks  = (w >> 5) & 15;
        const int xph = w >> 9;
        const int xp  = xph * 8 + xpl;               // 0..47
        const float* p = g + (size_t)(8 * ks + q) * HW_ + 2 * xp;
        const float2 vlo = *(const float2*)p;
        const float2 vhi = *(const float2*)(p + 4 * (size_t)HW_);
        const uint2 ev = make_uint2(f2tf(vlo.x), f2tf(vhi.x));
        const uint2 od = make_uint2(f2tf(vlo.y), f2tf(vhi.y));
        const int pos = (rowoff + xp) * RSW + 8 * ks + 2 * q;
        *(uint2*)(sm + BP0 + pos) = ev;
        *(uint2*)(sm + BP1 + pos) = od;
    }
}

__global__ void __launch_bounds__(192, 3)
corr_mma_kernel(const float* __restrict__ in1, const float* __restrict__ in2,
                float* __restrict__ out)
{
    extern __shared__ uint32_t sm[];
    const int tid  = threadIdx.x;
    const int warp = tid >> 5, lane = tid & 31;
    const int g8   = lane >> 2, tig = lane & 3;
    const int y = blockIdx.x, b = blockIdx.y;

    const int p  = warp & 1;          // parity
    const int mi = warp >> 1;         // m-tile index 0..2
    const int m0 = 16 * mi;
    const int sLo = (mi == 0) ? 1 : 0;
    const int sHi = (mi == 2) ? 3 : 4;

    // ---- stage A (in1 row y) into the tile buffers (scratch), rows u = 0..47 ----
    stage_row(in1 + (size_t)b * 128 * HW_ + (size_t)y * 96, sm, 0, tid);
    __syncthreads();

    // ---- load A fragments (16 k-steps x 4 regs) via LDS.64 pairs ----
    uint32_t areg[16][4];
    {
        const uint32_t* ap = sm + (p ? BP1 : BP0);
        const int r0 = (m0 + g8) * RSW, r1 = (m0 + g8 + 8) * RSW;
        #pragma unroll
        for (int ks = 0; ks < 16; ks++) {
            const int c = 8 * ks + 2 * tig;
            const uint2 ua = *(const uint2*)(ap + r0 + c);   // {k=tig, k=tig+4}
            const uint2 ub = *(const uint2*)(ap + r1 + c);
            areg[ks][0] = ua.x; areg[ks][1] = ub.x;
            areg[ks][2] = ua.y; areg[ks][3] = ub.y;
        }
    }
    __syncthreads();

    // ---- zero halo rows wS in {0,1} u [50,56) for both parities ----
    for (int i = tid; i < 8 * RSW; i += 192) {
        const int r = i / RSW, c = i - r * RSW;
        const int wS = (r < 2) ? r : (48 + r);
        sm[BP0 + wS * RSW + c] = 0u;
        sm[BP1 + wS * RSW + c] = 0u;
    }

    float* pad = (float*)(sm + PADOFF);
    const float inv = 1.0f / 128.0f;

    #pragma unroll 1
    for (int dy = 0; dy < 21; dy++) {
        const int y2 = y + 2 * (dy - 10);
        const bool valid = ((unsigned)y2 < 96u);

        if (valid)
            stage_row(in2 + (size_t)b * 128 * HW_ + (size_t)y2 * 96, sm, 2, tid);
        __syncthreads();

        if (valid) {
            float acc[5][4];
            #pragma unroll
            for (int s = 0; s < 5; s++)
                #pragma unroll
                for (int q = 0; q < 4; q++) acc[s][q] = 0.f;

            const uint32_t* bp = sm + (p ? BP1 : BP0);
            #pragma unroll
            for (int ks = 0; ks < 16; ks++) {
                #pragma unroll
                for (int s = 0; s < 5; s++) {
                    if (s < sLo || s > sHi) continue;
                    const int row = (m0 + 8 * s - 8 + g8) * RSW + 8 * ks + 2 * tig;
                    const uint2 bb = *(const uint2*)(bp + row);   // {k=tig, k=tig+4}
                    mma_tf32(acc[s], areg[ks], bb.x, bb.y);
                }
            }

            // scatter D frags into pad[j][x]
            const int x = 2 * (m0 + g8) + p;
            #pragma unroll
            for (int s = 0; s < 5; s++) {
                if (s < sLo || s > sHi) continue;
                const int j0 = 8 * s + 2 * tig - g8;
                if (j0 >= 0     && j0 < 21)     pad[j0 * PSTR + x]            = acc[s][0];
                if (j0 + 1 >= 0 && j0 + 1 < 21) pad[(j0 + 1) * PSTR + x]      = acc[s][1];
                const int j2 = j0 - 8;
                if (j2 >= 0     && j2 < 21)     pad[j2 * PSTR + x + 16]       = acc[s][2];
                if (j2 + 1 >= 0 && j2 + 1 < 21) pad[(j2 + 1) * PSTR + x + 16] = acc[s][3];
            }
        }
        __syncthreads();

        // masked coalesced copy (also emits zeros for invalid dy / out-of-window x2)
        const size_t obase = ((size_t)(b * 441 + dy * 21) * 96 + y) * 96;
        #pragma unroll 1
        for (int i = tid; i < 21 * 96; i += 192) {
            const int j = i / 96, x = i - 96 * j;
            const int x2 = x + 2 * j - 20;
            float v = 0.f;
            if (valid && (unsigned)x2 < 96u)
                v = pad[j * PSTR + x] * inv;
            out[obase + (size_t)j * HW_ + x] = v;
        }
    }
}

extern "C" void kernel_launch(void* const* d_in, const int* in_sizes, int n_in,
                              void* d_out, int out_size)
{
    const float* in1 = (const float*)d_in[0];
    const float* in2 = (const float*)d_in[1];
    float* out = (float*)d_out;

    cudaFuncSetAttribute(corr_mma_kernel, cudaFuncAttributeMaxDynamicSharedMemorySize, SMEM_BYTES);

    dim3 grid(96, 4);   // y, batch
    corr_mma_kernel<<<grid, 192, SMEM_BYTES>>>(in1, in2, out);
}

// round 17
// speedup vs baseline: 1.4391x; 1.4391x over previous
#include <cuda_runtime.h>
#include <cstdint>

// FlowNetC correlation via tf32 mma.sync band-GEMM with parity packing.
// R16 = R14 baseline (RSW=132, LDS.32 B-frags, STS.128 staging) +
//   PSTR 98->100 (pad scatter 8-way -> 2-way bank conflict),
//   affine masked copy loop (no div/mod),
//   staging unroll 2 (LDG MLP).

#define HW_  9216
#define RSW  132             // tile row stride (words); 132 % 32 = 4 -> conflict-free frags
#define BROWS 56
#define BP0  0
#define BP1  (BROWS*RSW + 16)          // 7408
#define PADOFF (BP1 + BROWS*RSW)       // 14800
#define PSTR 100                       // (2-PSTR) ≡ -2 mod 32 -> scatter 2-way max
#define SMEM_WORDS (PADOFF + 21*PSTR)  // 16900
#define SMEM_BYTES (SMEM_WORDS*4)      // 67600 -> 3 CTAs/SM

static __device__ __forceinline__ uint32_t f2tf(float f) {
    uint32_t r;
    asm("cvt.rna.tf32.f32 %0, %1;" : "=r"(r) : "f"(f));
    return r;
}

static __device__ __forceinline__ void mma_tf32(float (&d)[4], const uint32_t (&a)[4],
                                                uint32_t b0, uint32_t b1) {
    asm volatile(
        "mma.sync.aligned.m16n8k8.row.col.f32.tf32.tf32.f32 "
        "{%0,%1,%2,%3}, {%4,%5,%6,%7}, {%8,%9}, {%0,%1,%2,%3};"
        : "+f"(d[0]), "+f"(d[1]), "+f"(d[2]), "+f"(d[3])
        : "r"(a[0]), "r"(a[1]), "r"(a[2]), "r"(a[3]), "r"(b0), "r"(b1));
}

// Stage one image row (128 ch x 96 x, fp32) into the two parity tiles as tf32.
// Element (c, x) -> tile[p = x&1] row (rowoff + (x>>1)), word col c.
static __device__ __forceinline__ void stage_row(const float* __restrict__ g,
                                                 uint32_t* __restrict__ sm,
                                                 int rowoff, int tid)
{
    #pragma unroll 2
    for (int i = tid; i < 48 * 32; i += 192) {
        const int xp = i % 48, cp = i / 48;
        const float* pgl = g + (size_t)(4 * cp) * HW_ + 2 * xp;
        const float2 v0 = *(const float2*)(pgl);
        const float2 v1 = *(const float2*)(pgl + HW_);
        const float2 v2 = *(const float2*)(pgl + 2 * (size_t)HW_);
        const float2 v3 = *(const float2*)(pgl + 3 * (size_t)HW_);
        const uint4 ev = make_uint4(f2tf(v0.x), f2tf(v1.x), f2tf(v2.x), f2tf(v3.x));
        const uint4 od = make_uint4(f2tf(v0.y), f2tf(v1.y), f2tf(v2.y), f2tf(v3.y));
        const int r = (rowoff + xp) * RSW + 4 * cp;
        *(uint4*)(sm + BP0 + r) = ev;
        *(uint4*)(sm + BP1 + r) = od;
    }
}

__global__ void __launch_bounds__(192, 3)
corr_mma_kernel(const float* __restrict__ in1, const float* __restrict__ in2,
                float* __restrict__ out)
{
    extern __shared__ uint32_t sm[];
    const int tid  = threadIdx.x;
    const int warp = tid >> 5, lane = tid & 31;
    const int g8   = lane >> 2, tig = lane & 3;      // mma groupID / threadID-in-group
    const int y = blockIdx.x, b = blockIdx.y;

    const int p  = warp & 1;          // parity
    const int mi = warp >> 1;         // m-tile index 0..2
    const int m0 = 16 * mi;
    const int sLo = (mi == 0) ? 1 : 0;
    const int sHi = (mi == 2) ? 3 : 4;

    // ---- stage A (in1 row y) into the tile buffers (scratch), rows u = 0..47 ----
    stage_row(in1 + (size_t)b * 128 * HW_ + (size_t)y * 96, sm, 0, tid);
    __syncthreads();

    // ---- load A fragments for all 16 k-steps into registers ----
    uint32_t areg[16][4];
    {
        const uint32_t* ap = sm + (p ? BP1 : BP0);
        const int r0 = (m0 + g8) * RSW, r1 = (m0 + g8 + 8) * RSW;
        #pragma unroll
        for (int ks = 0; ks < 16; ks++) {
            const int c = 8 * ks + tig;
            areg[ks][0] = ap[r0 + c];
            areg[ks][1] = ap[r1 + c];
            areg[ks][2] = ap[r0 + c + 4];
            areg[ks][3] = ap[r1 + c + 4];
        }
    }
    __syncthreads();

    // ---- zero halo rows wS in {0,1} u [50,56) for both parities ----
    for (int i = tid; i < 8 * RSW; i += 192) {
        const int r = i / RSW, c = i - r * RSW;
        const int wS = (r < 2) ? r : (48 + r);
        sm[BP0 + wS * RSW + c] = 0u;
        sm[BP1 + wS * RSW + c] = 0u;
    }

    float* pad = (float*)(sm + PADOFF);
    const float inv = 1.0f / 128.0f;
    const int xcp = tid % 96;          // copy-loop column
    const int hcp = tid / 96;          // copy-loop j parity

    #pragma unroll 1
    for (int dy = 0; dy < 21; dy++) {
        const int y2 = y + 2 * (dy - 10);
        const bool valid = ((unsigned)y2 < 96u);

        if (valid)
            stage_row(in2 + (size_t)b * 128 * HW_ + (size_t)y2 * 96, sm, 2, tid);
        __syncthreads();

        if (valid) {
            float acc[5][4];
            #pragma unroll
            for (int s = 0; s < 5; s++)
                #pragma unroll
                for (int q = 0; q < 4; q++) acc[s][q] = 0.f;

            const uint32_t* bp = sm + (p ? BP1 : BP0);
            #pragma unroll
            for (int ks = 0; ks < 16; ks++) {
                #pragma unroll
                for (int s = 0; s < 5; s++) {
                    if (s < sLo || s > sHi) continue;
                    const int row = (m0 + 8 * s - 8 + g8) * RSW + 8 * ks + tig;
                    mma_tf32(acc[s], areg[ks], bp[row], bp[row + 4]);
                }
            }

            // scatter D frags into pad[j][x] (PSTR=100 -> max 2-way conflicts)
            const int x = 2 * (m0 + g8) + p;
            #pragma unroll
            for (int s = 0; s < 5; s++) {
                if (s < sLo || s > sHi) continue;
                const int j0 = 8 * s + 2 * tig - g8;       // w0 + 2tig - u_lo
                if (j0 >= 0     && j0 < 21)     pad[j0 * PSTR + x]            = acc[s][0];
                if (j0 + 1 >= 0 && j0 + 1 < 21) pad[(j0 + 1) * PSTR + x]      = acc[s][1];
                const int j2 = j0 - 8;
                if (j2 >= 0     && j2 < 21)     pad[j2 * PSTR + x + 16]       = acc[s][2];
                if (j2 + 1 >= 0 && j2 + 1 < 21) pad[(j2 + 1) * PSTR + x + 16] = acc[s][3];
            }
        }
        __syncthreads();

        // masked coalesced copy; affine indexing (x fixed per thread, j strided 2)
        const size_t obase = ((size_t)(b * 441 + dy * 21) * 96 + y) * 96;
        #pragma unroll
        for (int t = 0; t < 11; t++) {
            const int j = hcp + 2 * t;
            if (j < 21) {
                const int x2 = xcp + 2 * j - 20;
                float v = 0.f;
                if (valid && (unsigned)x2 < 96u)
                    v = pad[j * PSTR + xcp] * inv;
                out[obase + (size_t)j * HW_ + xcp] = v;
            }
        }
    }
}

extern "C" void kernel_launch(void* const* d_in, const int* in_sizes, int n_in,
                              void* d_out, int out_size)
{
    const float* in1 = (const float*)d_in[0];
    const float* in2 = (const float*)d_in[1];
    float* out = (float*)d_out;

    cudaFuncSetAttribute(corr_mma_kernel, cudaFuncAttributeMaxDynamicSharedMemorySize, SMEM_BYTES);

    dim3 grid(96, 4);   // y, batch
    corr_mma_kernel<<<grid, 192, SMEM_BYTES>>>(in1, in2, out);
}